// round 13
// baseline (speedup 1.0000x reference)
#include <cuda_runtime.h>
#include <cuda_fp16.h>
#include <cstdint>

// Problem constants
#define L_SEQ 16384
#define H_DIM 1024
#define P_DIM 512
#define N2P   1024        // 2*P
#define KDIM  1024        // K for both GEMMs
#define CHUNK 32
#define NCHUNK (L_SEQ / CHUNK)   // 512

// ---------------- device scratch (fp16) ----------------
__device__ __half g_W1[N2P * KDIM];    // weights
__device__ __half g_W2[H_DIM * N2P];
__device__ __half g_uh[L_SEQ * H_DIM]; // activations
__device__ __half g_Bu[L_SEQ * N2P];   // GEMM1 output (fp16)
__device__ __half g_xh[L_SEQ * N2P];
__device__ float2 g_lam[P_DIM];
__device__ float2 g_lampow[P_DIM];
__device__ float2 g_g[P_DIM];
__device__ float2 g_carry[NCHUNK * P_DIM];
__device__ float2 g_carryin[NCHUNK * P_DIM];
__device__ int    g_ctr;               // last-block ticket for fused scan

// ---------------- helpers ----------------
__device__ __forceinline__ uint32_t smem_u32(const void* p) {
    uint32_t a;
    asm("{ .reg .u64 t; cvta.to.shared.u64 t, %1; cvt.u32.u64 %0, t; }" : "=r"(a) : "l"(p));
    return a;
}
__device__ __forceinline__ void cp_async16(uint32_t dst, const void* src) {
    asm volatile("cp.async.cg.shared.global [%0], [%1], 16;" :: "r"(dst), "l"(src));
}
#define CP_COMMIT() asm volatile("cp.async.commit_group;" ::: "memory")
#define CP_WAIT(n)  asm volatile("cp.async.wait_group %0;" :: "n"(n) : "memory")

__device__ __forceinline__ void ldsm_x4(uint32_t* r, uint32_t addr) {
    asm volatile("ldmatrix.sync.aligned.m8n8.x4.shared.b16 {%0,%1,%2,%3}, [%4];"
        : "=r"(r[0]), "=r"(r[1]), "=r"(r[2]), "=r"(r[3]) : "r"(addr));
}
__device__ __forceinline__ void mma16816(float* d, const uint32_t* a, const uint32_t* b) {
    asm("mma.sync.aligned.m16n8k16.row.col.f32.f16.f16.f32 "
        "{%0,%1,%2,%3}, {%4,%5,%6,%7}, {%8,%9}, {%0,%1,%2,%3};"
        : "+f"(d[0]), "+f"(d[1]), "+f"(d[2]), "+f"(d[3])
        : "r"(a[0]), "r"(a[1]), "r"(a[2]), "r"(a[3]), "r"(b[0]), "r"(b[1]));
}

// ---------------- prep kernels ----------------
__global__ void prep_lambda(const float* __restrict__ Lre,
                            const float* __restrict__ Lim,
                            const float* __restrict__ log_step) {
    int p = threadIdx.x;
    if (p == 0) g_ctr = 0;                       // reset fused-scan ticket
    float lr = Lre[p], li = Lim[p];
    float dt = expf(log_step[p]);
    float ar = lr * dt, ai = li * dt;
    float er = expf(ar);
    float lam_r = er * cosf(ai);
    float lam_i = er * sinf(ai);
    g_lam[p] = make_float2(lam_r, lam_i);
    float er2 = expf(ar * (float)CHUNK);
    g_lampow[p] = make_float2(er2 * cosf(ai * (float)CHUNK), er2 * sinf(ai * (float)CHUNK));
    float nr = lam_r - 1.0f, ni = lam_i;
    float den = lr * lr + li * li;
    g_g[p] = make_float2((nr * lr + ni * li) / den, (ni * lr - nr * li) / den);
}

// fused: weight prep (blocks 0..2047) + u fp32->fp16 convert (blocks 2048..18431)
#define PREPW_BLOCKS 2048
__global__ void prep_big(const float* __restrict__ B, const float* __restrict__ C,
                         const float* __restrict__ u) {
    int bid = blockIdx.x;
    if (bid < PREPW_BLOCKS) {
        int idx = bid * blockDim.x + threadIdx.x;  // 0 .. P*H-1
        {   // W1 from B: idx = p*H + h
            int p = idx >> 10;
            int h = idx & (H_DIM - 1);
            float2 b = reinterpret_cast<const float2*>(B)[idx];
            float2 g = g_g[p];
            float vr = g.x * b.x - g.y * b.y;
            float vi = g.y * b.x + g.x * b.y;
            g_W1[p * KDIM + h]           = __float2half_rn(vr);
            g_W1[(P_DIM + p) * KDIM + h] = __float2half_rn(vi);
        }
        {   // W2 from C: idx = h*P + p
            int h = idx >> 9;
            int p = idx & (P_DIM - 1);
            float2 c = reinterpret_cast<const float2*>(C)[idx];
            g_W2[h * N2P + p]         = __float2half_rn(2.0f * c.x);
            g_W2[h * N2P + P_DIM + p] = __float2half_rn(-2.0f * c.y);
        }
    } else {
        int i = (bid - PREPW_BLOCKS) * blockDim.x + threadIdx.x;  // float4 idx
        float4 v = reinterpret_cast<const float4*>(u)[i];
        __half2 a = __floats2half2_rn(v.x, v.y);
        __half2 b = __floats2half2_rn(v.z, v.w);
        uint2 pk = make_uint2(*(uint32_t*)&a, *(uint32_t*)&b);
        reinterpret_cast<uint2*>(g_uh)[i] = pk;
    }
}

// ---------------- mma.sync fp16 GEMM ----------------
// 128x128 CTA tile; 256 threads, 2x4 warp grid, 64x32 warptile.
// BK=64: 128B rows, XOR-16B swizzle (ch ^= row&7), 3-stage cp.async pipeline,
// register double-buffered fragments across k16 groups.
#define BK 64
#define NSTG 3
#define PLANE_B (128 * 128)           // 16384
#define STAGE_B (2 * PLANE_B)         // 32768
#define SMEM_TOT (NSTG * STAGE_B)     // 98304

__device__ __forceinline__ void stage_load(uint32_t sb, int stage,
        const __half* __restrict__ pA, const __half* __restrict__ pB,
        int k0, int tid) {
    uint32_t base = sb + stage * STAGE_B;
#pragma unroll
    for (int i = 0; i < 4; i++) {
        int id = tid + i * 256;               // 0..1023
        int row = id >> 3, ch = id & 7;
        uint32_t dst = base + (uint32_t)(row * 128 + ((ch ^ (row & 7)) << 4));
        size_t gof = (size_t)row * KDIM + k0 + ch * 8;
        cp_async16(dst,           pA + gof);
        cp_async16(dst + PLANE_B, pB + gof);
    }
}

template <bool EPI>
__global__ void __launch_bounds__(256, 2) mma_gemm(
    const __half* __restrict__ A, const __half* __restrict__ Bm,
    void* __restrict__ Co,
    const __half* __restrict__ U, const float* __restrict__ Dv) {
    extern __shared__ __align__(128) char smem[];
    const uint32_t sb = smem_u32(smem);
    const int tid = threadIdx.x;
    const int lane = tid & 31, wid = tid >> 5;
    const int wm = wid & 1, wn = wid >> 1;           // 2x4 warp grid, 64x32 warptile
    const int lq = lane >> 2, lc = lane & 3;
    const int brow = blockIdx.y, bcol = blockIdx.x;

    const __half* pA = A  + (size_t)brow * 128 * KDIM;
    const __half* pB = Bm + (size_t)bcol * 128 * KDIM;

    const int arow = (lane & 7) + ((lane >> 3) & 1) * 8;
    const int akb  = (lane >> 4) & 1;
    const int axor = arow & 7;
    const int brow_l = (lane & 7) + ((lane >> 4) & 1) * 8;
    const int bkb    = (lane >> 3) & 1;
    const int bxor   = brow_l & 7;

    const uint32_t abase = (uint32_t)((wm * 64 + arow) * 128);
    const uint32_t bbase = PLANE_B + (uint32_t)((wn * 32 + brow_l) * 128);

    float acc[4][4][4] = {};
    uint32_t ah[2][4][4], bh[2][2][4];   // double-buffered fragments

    stage_load(sb, 0, pA, pB, 0, tid);    CP_COMMIT();
    stage_load(sb, 1, pA, pB, BK, tid);   CP_COMMIT();

    const int NS = KDIM / BK;     // 16
    int sidx = 0;
    for (int s = 0; s < NS; s++) {
        CP_WAIT(1);
        __syncthreads();
        if (s + 2 < NS) {
            int tgt = sidx + 2; if (tgt >= NSTG) tgt -= NSTG;
            stage_load(sb, tgt, pA, pB, (s + 2) * BK, tid);
        }
        CP_COMMIT();

        const uint32_t st = sb + sidx * STAGE_B;

#pragma unroll
        for (int mt = 0; mt < 4; mt++)
            ldsm_x4(ah[0][mt], st + abase + (uint32_t)(mt * 16 * 128)
                               + (uint32_t)((akb ^ axor) << 4));
#pragma unroll
        for (int ntp = 0; ntp < 2; ntp++)
            ldsm_x4(bh[0][ntp], st + bbase + (uint32_t)(ntp * 16 * 128)
                               + (uint32_t)((bkb ^ bxor) << 4));

#pragma unroll
        for (int k16 = 0; k16 < 4; k16++) {
            const int cur = k16 & 1, nxt = cur ^ 1;
            if (k16 < 3) {
                const int kn = k16 + 1;
#pragma unroll
                for (int mt = 0; mt < 4; mt++)
                    ldsm_x4(ah[nxt][mt], st + abase + (uint32_t)(mt * 16 * 128)
                                       + (uint32_t)(((kn * 2 + akb) ^ axor) << 4));
#pragma unroll
                for (int ntp = 0; ntp < 2; ntp++)
                    ldsm_x4(bh[nxt][ntp], st + bbase + (uint32_t)(ntp * 16 * 128)
                                        + (uint32_t)(((kn * 2 + bkb) ^ bxor) << 4));
            }
#pragma unroll
            for (int ntp = 0; ntp < 2; ntp++)
#pragma unroll
                for (int sub = 0; sub < 2; sub++) {
                    const uint32_t* bp = &bh[cur][ntp][sub * 2];
#pragma unroll
                    for (int mt = 0; mt < 4; mt++)
                        mma16816(acc[mt][ntp * 2 + sub], ah[cur][mt], bp);
                }
        }
        sidx++; if (sidx == NSTG) sidx = 0;
    }

    // epilogue
#pragma unroll
    for (int mt = 0; mt < 4; mt++) {
        const int row0 = brow * 128 + wm * 64 + mt * 16 + lq;
#pragma unroll
        for (int nt = 0; nt < 4; nt++) {
            const int col = bcol * 128 + wn * 32 + nt * 8 + lc * 2;
            const float* d = acc[mt][nt];
            if (EPI) {
                float* o = (float*)Co;
                float2 dd = *reinterpret_cast<const float2*>(Dv + col);
                __half2 uh0 = *reinterpret_cast<const __half2*>(U + (size_t)row0 * 1024 + col);
                __half2 uh1 = *reinterpret_cast<const __half2*>(U + (size_t)(row0 + 8) * 1024 + col);
                float2 u0 = __half22float2(uh0);
                float2 u1 = __half22float2(uh1);
                float2 v0 = make_float2(fmaf(dd.x, u0.x, d[0]), fmaf(dd.y, u0.y, d[1]));
                float2 v1 = make_float2(fmaf(dd.x, u1.x, d[2]), fmaf(dd.y, u1.y, d[3]));
                *reinterpret_cast<float2*>(o + (size_t)row0 * 1024 + col) = v0;
                *reinterpret_cast<float2*>(o + (size_t)(row0 + 8) * 1024 + col) = v1;
            } else {
                __half* o = (__half*)Co;
                __half2 h0 = __floats2half2_rn(d[0], d[1]);
                __half2 h1 = __floats2half2_rn(d[2], d[3]);
                *reinterpret_cast<__half2*>(o + (size_t)row0 * 1024 + col) = h0;
                *reinterpret_cast<__half2*>(o + (size_t)(row0 + 8) * 1024 + col) = h1;
            }
        }
    }
}

// ---------------- fused scan phases 1+2 ----------------
// NCHUNK=512 blocks x 256 threads (2 p each). Each block computes its chunk
// aggregate; the LAST block also runs the 512-step serial exclusive scan over
// chunk carries with software-pipelined batch-8 loads.
#define P2B 8
__global__ void scan_phase12() {
    int c  = blockIdx.x;
    int pq = threadIdx.x;          // 0..255
    int p0 = pq * 2;
    float2 lam0 = g_lam[p0], lam1 = g_lam[p0 + 1];
    float b0r = 0.f, b0i = 0.f, b1r = 0.f, b1i = 0.f;
    const __half* base = g_Bu + (size_t)(c * CHUNK) * N2P;
#pragma unroll 4
    for (int i = 0; i < CHUNK; i++) {
        float2 re = __half22float2(*reinterpret_cast<const __half2*>(base + i * N2P + p0));
        float2 im = __half22float2(*reinterpret_cast<const __half2*>(base + i * N2P + P_DIM + p0));
        float n0r = fmaf(lam0.x, b0r, fmaf(-lam0.y, b0i, re.x));
        float n0i = fmaf(lam0.x, b0i, fmaf(lam0.y, b0r, im.x));
        float n1r = fmaf(lam1.x, b1r, fmaf(-lam1.y, b1i, re.y));
        float n1i = fmaf(lam1.x, b1i, fmaf(lam1.y, b1r, im.y));
        b0r = n0r; b0i = n0i; b1r = n1r; b1i = n1i;
    }
    g_carry[c * P_DIM + p0]     = make_float2(b0r, b0i);
    g_carry[c * P_DIM + p0 + 1] = make_float2(b1r, b1i);

    // last-block ticket
    __threadfence();
    __shared__ int is_last;
    if (threadIdx.x == 0)
        is_last = (atomicAdd(&g_ctr, 1) == gridDim.x - 1) ? 1 : 0;
    __syncthreads();
    if (!is_last) return;

    // phase 2: exclusive scan over 512 chunk carries; 2 p per thread.
    // software-pipelined batches of P2B.
    float2 A0 = g_lampow[p0], A1 = g_lampow[p0 + 1];
    float s0r = 0.f, s0i = 0.f, s1r = 0.f, s1i = 0.f;
    float2 v0[2][P2B], v1[2][P2B];
    // prefetch batch 0
#pragma unroll
    for (int j = 0; j < P2B; j++) {
        v0[0][j] = g_carry[j * P_DIM + p0];
        v1[0][j] = g_carry[j * P_DIM + p0 + 1];
    }
    for (int cc = 0; cc < NCHUNK; cc += P2B) {
        const int buf = (cc / P2B) & 1;
        if (cc + P2B < NCHUNK) {
#pragma unroll
            for (int j = 0; j < P2B; j++) {
                v0[buf ^ 1][j] = g_carry[(cc + P2B + j) * P_DIM + p0];
                v1[buf ^ 1][j] = g_carry[(cc + P2B + j) * P_DIM + p0 + 1];
            }
        }
#pragma unroll
        for (int j = 0; j < P2B; j++) {
            g_carryin[(cc + j) * P_DIM + p0]     = make_float2(s0r, s0i);
            g_carryin[(cc + j) * P_DIM + p0 + 1] = make_float2(s1r, s1i);
            float n0r = fmaf(A0.x, s0r, fmaf(-A0.y, s0i, v0[buf][j].x));
            float n0i = fmaf(A0.x, s0i, fmaf(A0.y, s0r, v0[buf][j].y));
            float n1r = fmaf(A1.x, s1r, fmaf(-A1.y, s1i, v1[buf][j].x));
            float n1i = fmaf(A1.x, s1i, fmaf(A1.y, s1r, v1[buf][j].y));
            s0r = n0r; s0i = n0i; s1r = n1r; s1i = n1i;
        }
    }
}

// ---------------- scan phase 3 ----------------
__global__ void scan_phase3() {
    int idx = blockIdx.x * blockDim.x + threadIdx.x;
    int pq = idx & (P_DIM / 2 - 1);
    int c  = idx >> 8;
    int p0 = pq * 2;
    float2 lam0 = g_lam[p0], lam1 = g_lam[p0 + 1];
    float2 c0 = g_carryin[c * P_DIM + p0];
    float2 c1 = g_carryin[c * P_DIM + p0 + 1];
    float x0r = c0.x, x0i = c0.y, x1r = c1.x, x1i = c1.y;
    const __half* base = g_Bu + (size_t)(c * CHUNK) * N2P;
    __half* oh = g_xh + (size_t)(c * CHUNK) * N2P;
#pragma unroll 4
    for (int i = 0; i < CHUNK; i++) {
        float2 re = __half22float2(*reinterpret_cast<const __half2*>(base + i * N2P + p0));
        float2 im = __half22float2(*reinterpret_cast<const __half2*>(base + i * N2P + P_DIM + p0));
        float n0r = fmaf(lam0.x, x0r, fmaf(-lam0.y, x0i, re.x));
        float n0i = fmaf(lam0.x, x0i, fmaf(lam0.y, x0r, im.x));
        float n1r = fmaf(lam1.x, x1r, fmaf(-lam1.y, x1i, re.y));
        float n1i = fmaf(lam1.x, x1i, fmaf(lam1.y, x1r, im.y));
        x0r = n0r; x0i = n0i; x1r = n1r; x1i = n1i;
        *reinterpret_cast<__half2*>(oh + i * N2P + p0)         = __floats2half2_rn(x0r, x1r);
        *reinterpret_cast<__half2*>(oh + i * N2P + P_DIM + p0) = __floats2half2_rn(x0i, x1i);
    }
}

// ---------------- launcher ----------------
extern "C" void kernel_launch(void* const* d_in, const int* in_sizes, int n_in,
                              void* d_out, int out_size) {
    const float* u        = (const float*)d_in[0];
    const float* Lre      = (const float*)d_in[1];
    const float* Lim      = (const float*)d_in[2];
    const float* B        = (const float*)d_in[3];
    const float* C        = (const float*)d_in[4];
    const float* D        = (const float*)d_in[5];
    const float* log_step = (const float*)d_in[6];
    float* out = (float*)d_out;

    cudaFuncSetAttribute(mma_gemm<false>, cudaFuncAttributeMaxDynamicSharedMemorySize, SMEM_TOT);
    cudaFuncSetAttribute(mma_gemm<true>,  cudaFuncAttributeMaxDynamicSharedMemorySize, SMEM_TOT);

    __half *uh, *w1, *w2, *xh, *bu;
    cudaGetSymbolAddress((void**)&uh, g_uh);
    cudaGetSymbolAddress((void**)&w1, g_W1);
    cudaGetSymbolAddress((void**)&w2, g_W2);
    cudaGetSymbolAddress((void**)&xh, g_xh);
    cudaGetSymbolAddress((void**)&bu, g_Bu);

    prep_lambda<<<1, P_DIM>>>(Lre, Lim, log_step);
    prep_big<<<PREPW_BLOCKS + (L_SEQ * H_DIM / 4) / 256, 256>>>(B, C, u);

    // GEMM1: Bu = u @ W1  (fp16 out)
    mma_gemm<false><<<dim3(N2P / 128, L_SEQ / 128), 256, SMEM_TOT>>>(
        uh, w1, bu, nullptr, nullptr);

    scan_phase12<<<NCHUNK, 256>>>();
    scan_phase3<<<(NCHUNK * P_DIM / 2) / 256, 256>>>();

    // GEMM2: out = xs @ W2 + D .* u
    mma_gemm<true><<<dim3(H_DIM / 128, L_SEQ / 128), 256, SMEM_TOT>>>(
        xh, w2, out, uh, D);
}

// round 14
// speedup vs baseline: 1.2562x; 1.2562x over previous
#include <cuda_runtime.h>
#include <cuda_fp16.h>
#include <cstdint>

// Problem constants
#define L_SEQ 16384
#define H_DIM 1024
#define P_DIM 512
#define N2P   1024        // 2*P
#define KDIM  1024        // K for both GEMMs
#define CHUNK 64
#define NCHUNK (L_SEQ / CHUNK)   // 256

// ---------------- device scratch (fp16) ----------------
__device__ __half g_W1[N2P * KDIM];    // weights
__device__ __half g_W2[H_DIM * N2P];
__device__ __half g_uh[L_SEQ * H_DIM]; // activations
__device__ __half g_Bu[L_SEQ * N2P];   // GEMM1 output (fp16)
__device__ __half g_xh[L_SEQ * N2P];
__device__ float2 g_lam[P_DIM];
__device__ float2 g_lampow[P_DIM];
__device__ float2 g_g[P_DIM];
__device__ float2 g_carry[NCHUNK * P_DIM];
__device__ float2 g_carryin[NCHUNK * P_DIM];
__device__ int    g_ctr;               // last-block ticket for fused scan

// ---------------- helpers ----------------
__device__ __forceinline__ uint32_t smem_u32(const void* p) {
    uint32_t a;
    asm("{ .reg .u64 t; cvta.to.shared.u64 t, %1; cvt.u32.u64 %0, t; }" : "=r"(a) : "l"(p));
    return a;
}
__device__ __forceinline__ void cp_async16(uint32_t dst, const void* src) {
    asm volatile("cp.async.cg.shared.global [%0], [%1], 16;" :: "r"(dst), "l"(src));
}
#define CP_COMMIT() asm volatile("cp.async.commit_group;" ::: "memory")
#define CP_WAIT(n)  asm volatile("cp.async.wait_group %0;" :: "n"(n) : "memory")

__device__ __forceinline__ void ldsm_x4(uint32_t* r, uint32_t addr) {
    asm volatile("ldmatrix.sync.aligned.m8n8.x4.shared.b16 {%0,%1,%2,%3}, [%4];"
        : "=r"(r[0]), "=r"(r[1]), "=r"(r[2]), "=r"(r[3]) : "r"(addr));
}
__device__ __forceinline__ void mma16816(float* d, const uint32_t* a, const uint32_t* b) {
    asm("mma.sync.aligned.m16n8k16.row.col.f32.f16.f16.f32 "
        "{%0,%1,%2,%3}, {%4,%5,%6,%7}, {%8,%9}, {%0,%1,%2,%3};"
        : "+f"(d[0]), "+f"(d[1]), "+f"(d[2]), "+f"(d[3])
        : "r"(a[0]), "r"(a[1]), "r"(a[2]), "r"(a[3]), "r"(b[0]), "r"(b[1]));
}

// ---------------- prep kernels ----------------
__global__ void prep_lambda(const float* __restrict__ Lre,
                            const float* __restrict__ Lim,
                            const float* __restrict__ log_step) {
    int p = threadIdx.x;
    if (p == 0) g_ctr = 0;                       // reset fused-scan ticket
    float lr = Lre[p], li = Lim[p];
    float dt = expf(log_step[p]);
    float ar = lr * dt, ai = li * dt;
    float er = expf(ar);
    float lam_r = er * cosf(ai);
    float lam_i = er * sinf(ai);
    g_lam[p] = make_float2(lam_r, lam_i);
    float er2 = expf(ar * (float)CHUNK);
    g_lampow[p] = make_float2(er2 * cosf(ai * (float)CHUNK), er2 * sinf(ai * (float)CHUNK));
    float nr = lam_r - 1.0f, ni = lam_i;
    float den = lr * lr + li * li;
    g_g[p] = make_float2((nr * lr + ni * li) / den, (ni * lr - nr * li) / den);
}

// fused: weight prep (blocks 0..2047) + u fp32->fp16 convert (blocks 2048..18431)
#define PREPW_BLOCKS 2048
__global__ void prep_big(const float* __restrict__ B, const float* __restrict__ C,
                         const float* __restrict__ u) {
    int bid = blockIdx.x;
    if (bid < PREPW_BLOCKS) {
        int idx = bid * blockDim.x + threadIdx.x;  // 0 .. P*H-1
        {   // W1 from B: idx = p*H + h
            int p = idx >> 10;
            int h = idx & (H_DIM - 1);
            float2 b = reinterpret_cast<const float2*>(B)[idx];
            float2 g = g_g[p];
            float vr = g.x * b.x - g.y * b.y;
            float vi = g.y * b.x + g.x * b.y;
            g_W1[p * KDIM + h]           = __float2half_rn(vr);
            g_W1[(P_DIM + p) * KDIM + h] = __float2half_rn(vi);
        }
        {   // W2 from C: idx = h*P + p
            int h = idx >> 9;
            int p = idx & (P_DIM - 1);
            float2 c = reinterpret_cast<const float2*>(C)[idx];
            g_W2[h * N2P + p]         = __float2half_rn(2.0f * c.x);
            g_W2[h * N2P + P_DIM + p] = __float2half_rn(-2.0f * c.y);
        }
    } else {
        int i = (bid - PREPW_BLOCKS) * blockDim.x + threadIdx.x;  // float4 idx
        float4 v = reinterpret_cast<const float4*>(u)[i];
        __half2 a = __floats2half2_rn(v.x, v.y);
        __half2 b = __floats2half2_rn(v.z, v.w);
        uint2 pk = make_uint2(*(uint32_t*)&a, *(uint32_t*)&b);
        reinterpret_cast<uint2*>(g_uh)[i] = pk;
    }
}

// ---------------- mma.sync fp16 GEMM ----------------
// 128x128 CTA tile; 256 threads, 2x4 warp grid, 64x32 warptile.
// BK=64: 128B rows, XOR-16B swizzle (ch ^= row&7), 3-stage cp.async pipeline,
// register double-buffered fragments across k16 groups.
#define BK 64
#define NSTG 3
#define PLANE_B (128 * 128)           // 16384
#define STAGE_B (2 * PLANE_B)         // 32768
#define SMEM_TOT (NSTG * STAGE_B)     // 98304

__device__ __forceinline__ void stage_load(uint32_t sb, int stage,
        const __half* __restrict__ pA, const __half* __restrict__ pB,
        int k0, int tid) {
    uint32_t base = sb + stage * STAGE_B;
#pragma unroll
    for (int i = 0; i < 4; i++) {
        int id = tid + i * 256;               // 0..1023
        int row = id >> 3, ch = id & 7;
        uint32_t dst = base + (uint32_t)(row * 128 + ((ch ^ (row & 7)) << 4));
        size_t gof = (size_t)row * KDIM + k0 + ch * 8;
        cp_async16(dst,           pA + gof);
        cp_async16(dst + PLANE_B, pB + gof);
    }
}

template <bool EPI>
__global__ void __launch_bounds__(256, 2) mma_gemm(
    const __half* __restrict__ A, const __half* __restrict__ Bm,
    void* __restrict__ Co,
    const __half* __restrict__ U, const float* __restrict__ Dv) {
    extern __shared__ __align__(128) char smem[];
    const uint32_t sb = smem_u32(smem);
    const int tid = threadIdx.x;
    const int lane = tid & 31, wid = tid >> 5;
    const int wm = wid & 1, wn = wid >> 1;           // 2x4 warp grid, 64x32 warptile
    const int lq = lane >> 2, lc = lane & 3;
    const int brow = blockIdx.y, bcol = blockIdx.x;

    const __half* pA = A  + (size_t)brow * 128 * KDIM;
    const __half* pB = Bm + (size_t)bcol * 128 * KDIM;

    const int arow = (lane & 7) + ((lane >> 3) & 1) * 8;
    const int akb  = (lane >> 4) & 1;
    const int axor = arow & 7;
    const int brow_l = (lane & 7) + ((lane >> 4) & 1) * 8;
    const int bkb    = (lane >> 3) & 1;
    const int bxor   = brow_l & 7;

    const uint32_t abase = (uint32_t)((wm * 64 + arow) * 128);
    const uint32_t bbase = PLANE_B + (uint32_t)((wn * 32 + brow_l) * 128);

    float acc[4][4][4] = {};
    uint32_t ah[2][4][4], bh[2][2][4];   // double-buffered fragments

    stage_load(sb, 0, pA, pB, 0, tid);    CP_COMMIT();
    stage_load(sb, 1, pA, pB, BK, tid);   CP_COMMIT();

    const int NS = KDIM / BK;     // 16
    int sidx = 0;
    for (int s = 0; s < NS; s++) {
        CP_WAIT(1);
        __syncthreads();
        if (s + 2 < NS) {
            int tgt = sidx + 2; if (tgt >= NSTG) tgt -= NSTG;
            stage_load(sb, tgt, pA, pB, (s + 2) * BK, tid);
        }
        CP_COMMIT();

        const uint32_t st = sb + sidx * STAGE_B;

#pragma unroll
        for (int mt = 0; mt < 4; mt++)
            ldsm_x4(ah[0][mt], st + abase + (uint32_t)(mt * 16 * 128)
                               + (uint32_t)((akb ^ axor) << 4));
#pragma unroll
        for (int ntp = 0; ntp < 2; ntp++)
            ldsm_x4(bh[0][ntp], st + bbase + (uint32_t)(ntp * 16 * 128)
                               + (uint32_t)((bkb ^ bxor) << 4));

#pragma unroll
        for (int k16 = 0; k16 < 4; k16++) {
            const int cur = k16 & 1, nxt = cur ^ 1;
            if (k16 < 3) {
                const int kn = k16 + 1;
#pragma unroll
                for (int mt = 0; mt < 4; mt++)
                    ldsm_x4(ah[nxt][mt], st + abase + (uint32_t)(mt * 16 * 128)
                                       + (uint32_t)(((kn * 2 + akb) ^ axor) << 4));
#pragma unroll
                for (int ntp = 0; ntp < 2; ntp++)
                    ldsm_x4(bh[nxt][ntp], st + bbase + (uint32_t)(ntp * 16 * 128)
                                        + (uint32_t)(((kn * 2 + bkb) ^ bxor) << 4));
            }
#pragma unroll
            for (int ntp = 0; ntp < 2; ntp++)
#pragma unroll
                for (int sub = 0; sub < 2; sub++) {
                    const uint32_t* bp = &bh[cur][ntp][sub * 2];
#pragma unroll
                    for (int mt = 0; mt < 4; mt++)
                        mma16816(acc[mt][ntp * 2 + sub], ah[cur][mt], bp);
                }
        }
        sidx++; if (sidx == NSTG) sidx = 0;
    }

    // epilogue
#pragma unroll
    for (int mt = 0; mt < 4; mt++) {
        const int row0 = brow * 128 + wm * 64 + mt * 16 + lq;
#pragma unroll
        for (int nt = 0; nt < 4; nt++) {
            const int col = bcol * 128 + wn * 32 + nt * 8 + lc * 2;
            const float* d = acc[mt][nt];
            if (EPI) {
                float* o = (float*)Co;
                float2 dd = *reinterpret_cast<const float2*>(Dv + col);
                __half2 uh0 = *reinterpret_cast<const __half2*>(U + (size_t)row0 * 1024 + col);
                __half2 uh1 = *reinterpret_cast<const __half2*>(U + (size_t)(row0 + 8) * 1024 + col);
                float2 u0 = __half22float2(uh0);
                float2 u1 = __half22float2(uh1);
                float2 v0 = make_float2(fmaf(dd.x, u0.x, d[0]), fmaf(dd.y, u0.y, d[1]));
                float2 v1 = make_float2(fmaf(dd.x, u1.x, d[2]), fmaf(dd.y, u1.y, d[3]));
                *reinterpret_cast<float2*>(o + (size_t)row0 * 1024 + col) = v0;
                *reinterpret_cast<float2*>(o + (size_t)(row0 + 8) * 1024 + col) = v1;
            } else {
                __half* o = (__half*)Co;
                __half2 h0 = __floats2half2_rn(d[0], d[1]);
                __half2 h1 = __floats2half2_rn(d[2], d[3]);
                *reinterpret_cast<__half2*>(o + (size_t)row0 * 1024 + col) = h0;
                *reinterpret_cast<__half2*>(o + (size_t)(row0 + 8) * 1024 + col) = h1;
            }
        }
    }
}

// ---------------- fused scan phases 1+2 ----------------
// NCHUNK=256 blocks x 512 threads (1 p each). Each block computes its chunk
// aggregate; the LAST block also runs the 256-step serial exclusive scan over
// chunk carries (batch-4, fully unrolled, compile-time indexed).
__global__ void scan_phase12() {
    int c = blockIdx.x;
    int p = threadIdx.x;           // 0..511
    float2 lam = g_lam[p];
    float br = 0.f, bi = 0.f;
    const __half* base = g_Bu + (size_t)(c * CHUNK) * N2P;
#pragma unroll 4
    for (int i = 0; i < CHUNK; i++) {
        float ur = __half2float(base[i * N2P + p]);
        float ui = __half2float(base[i * N2P + P_DIM + p]);
        float nr = fmaf(lam.x, br, fmaf(-lam.y, bi, ur));
        float ni = fmaf(lam.x, bi, fmaf(lam.y, br, ui));
        br = nr; bi = ni;
    }
    g_carry[c * P_DIM + p] = make_float2(br, bi);

    // last-block ticket
    __threadfence();
    __shared__ int is_last;
    if (threadIdx.x == 0)
        is_last = (atomicAdd(&g_ctr, 1) == gridDim.x - 1) ? 1 : 0;
    __syncthreads();
    if (!is_last) return;

    // phase 2: exclusive scan over 256 chunk carries; 1 p per thread.
    float2 Ap = g_lampow[p];
    float sr = 0.f, si = 0.f;
    for (int cc = 0; cc < NCHUNK; cc += 4) {
        float2 v[4];
#pragma unroll
        for (int j = 0; j < 4; j++)
            v[j] = g_carry[(cc + j) * P_DIM + p];
#pragma unroll
        for (int j = 0; j < 4; j++) {
            g_carryin[(cc + j) * P_DIM + p] = make_float2(sr, si);
            float nr = fmaf(Ap.x, sr, fmaf(-Ap.y, si, v[j].x));
            float ni = fmaf(Ap.x, si, fmaf(Ap.y, sr, v[j].y));
            sr = nr; si = ni;
        }
    }
}

// ---------------- scan phase 3 ----------------
// NCHUNK*P threads (1 p each), 512 blocks x 256.
__global__ void scan_phase3() {
    int idx = blockIdx.x * blockDim.x + threadIdx.x;
    int p = idx & (P_DIM - 1);
    int c = idx >> 9;
    float2 lam = g_lam[p];
    float2 x0 = g_carryin[c * P_DIM + p];
    float xr = x0.x, xi = x0.y;
    const __half* base = g_Bu + (size_t)(c * CHUNK) * N2P;
    __half* oh = g_xh + (size_t)(c * CHUNK) * N2P;
#pragma unroll 4
    for (int i = 0; i < CHUNK; i++) {
        float ur = __half2float(base[i * N2P + p]);
        float ui = __half2float(base[i * N2P + P_DIM + p]);
        float nr = fmaf(lam.x, xr, fmaf(-lam.y, xi, ur));
        float ni = fmaf(lam.x, xi, fmaf(lam.y, xr, ui));
        xr = nr; xi = ni;
        oh[i * N2P + p]         = __float2half_rn(xr);
        oh[i * N2P + P_DIM + p] = __float2half_rn(xi);
    }
}

// ---------------- launcher ----------------
extern "C" void kernel_launch(void* const* d_in, const int* in_sizes, int n_in,
                              void* d_out, int out_size) {
    const float* u        = (const float*)d_in[0];
    const float* Lre      = (const float*)d_in[1];
    const float* Lim      = (const float*)d_in[2];
    const float* B        = (const float*)d_in[3];
    const float* C        = (const float*)d_in[4];
    const float* D        = (const float*)d_in[5];
    const float* log_step = (const float*)d_in[6];
    float* out = (float*)d_out;

    cudaFuncSetAttribute(mma_gemm<false>, cudaFuncAttributeMaxDynamicSharedMemorySize, SMEM_TOT);
    cudaFuncSetAttribute(mma_gemm<true>,  cudaFuncAttributeMaxDynamicSharedMemorySize, SMEM_TOT);

    __half *uh, *w1, *w2, *xh, *bu;
    cudaGetSymbolAddress((void**)&uh, g_uh);
    cudaGetSymbolAddress((void**)&w1, g_W1);
    cudaGetSymbolAddress((void**)&w2, g_W2);
    cudaGetSymbolAddress((void**)&xh, g_xh);
    cudaGetSymbolAddress((void**)&bu, g_Bu);

    prep_lambda<<<1, P_DIM>>>(Lre, Lim, log_step);
    prep_big<<<PREPW_BLOCKS + (L_SEQ * H_DIM / 4) / 256, 256>>>(B, C, u);

    // GEMM1: Bu = u @ W1  (fp16 out)
    mma_gemm<false><<<dim3(N2P / 128, L_SEQ / 128), 256, SMEM_TOT>>>(
        uh, w1, bu, nullptr, nullptr);

    scan_phase12<<<NCHUNK, P_DIM>>>();
    scan_phase3<<<(NCHUNK * P_DIM) / 256, 256>>>();

    // GEMM2: out = xs @ W2 + D .* u
    mma_gemm<true><<<dim3(H_DIM / 128, L_SEQ / 128), 256, SMEM_TOT>>>(
        xh, w2, out, uh, D);
}

// round 15
// speedup vs baseline: 1.3518x; 1.0761x over previous
#include <cuda_runtime.h>
#include <cuda_fp16.h>
#include <cstdint>

// Problem constants
#define L_SEQ 16384
#define H_DIM 1024
#define P_DIM 512
#define N2P   1024        // 2*P
#define KDIM  1024        // K for both GEMMs
#define CHUNK 64
#define NCHUNK (L_SEQ / CHUNK)   // 256

// ---------------- device scratch (fp16) ----------------
__device__ __half g_W1[N2P * KDIM];    // weights
__device__ __half g_W2[H_DIM * N2P];
__device__ __half g_uh[L_SEQ * H_DIM]; // activations
__device__ __half g_Bu[L_SEQ * N2P];   // GEMM1 output (fp16)
__device__ __half g_xh[L_SEQ * N2P];
__device__ float2 g_lam[P_DIM];
__device__ float2 g_lampow[P_DIM];
__device__ float2 g_carry[NCHUNK * P_DIM];
__device__ int    g_flag[NCHUNK];      // per-chunk aggregate-published flags

// ---------------- helpers ----------------
__device__ __forceinline__ uint32_t smem_u32(const void* p) {
    uint32_t a;
    asm("{ .reg .u64 t; cvta.to.shared.u64 t, %1; cvt.u32.u64 %0, t; }" : "=r"(a) : "l"(p));
    return a;
}
__device__ __forceinline__ void cp_async16(uint32_t dst, const void* src) {
    asm volatile("cp.async.cg.shared.global [%0], [%1], 16;" :: "r"(dst), "l"(src));
}
#define CP_COMMIT() asm volatile("cp.async.commit_group;" ::: "memory")
#define CP_WAIT(n)  asm volatile("cp.async.wait_group %0;" :: "n"(n) : "memory")

__device__ __forceinline__ void ldsm_x4(uint32_t* r, uint32_t addr) {
    asm volatile("ldmatrix.sync.aligned.m8n8.x4.shared.b16 {%0,%1,%2,%3}, [%4];"
        : "=r"(r[0]), "=r"(r[1]), "=r"(r[2]), "=r"(r[3]) : "r"(addr));
}
__device__ __forceinline__ void mma16816(float* d, const uint32_t* a, const uint32_t* b) {
    asm("mma.sync.aligned.m16n8k16.row.col.f32.f16.f16.f32 "
        "{%0,%1,%2,%3}, {%4,%5,%6,%7}, {%8,%9}, {%0,%1,%2,%3};"
        : "+f"(d[0]), "+f"(d[1]), "+f"(d[2]), "+f"(d[3])
        : "r"(a[0]), "r"(a[1]), "r"(a[2]), "r"(a[3]), "r"(b[0]), "r"(b[1]));
}

// ---------------- prep kernels ----------------
__global__ void prep_lambda(const float* __restrict__ Lre,
                            const float* __restrict__ Lim,
                            const float* __restrict__ log_step) {
    int p = threadIdx.x;
    if (p < NCHUNK) g_flag[p] = 0;               // reset lookback flags
    float lr = Lre[p], li = Lim[p];
    float dt = expf(log_step[p]);
    float ar = lr * dt, ai = li * dt;
    float er = expf(ar);
    float lam_r = er * cosf(ai);
    float lam_i = er * sinf(ai);
    g_lam[p] = make_float2(lam_r, lam_i);
    float er2 = expf(ar * (float)CHUNK);
    g_lampow[p] = make_float2(er2 * cosf(ai * (float)CHUNK), er2 * sinf(ai * (float)CHUNK));
}

// fused: weight prep (blocks 0..2047) + u fp32->fp16 convert (blocks 2048..18431)
// W1 needs g = (lam-1)/Lambda — recomputed here from raw inputs (cheap, avoids dep).
#define PREPW_BLOCKS 2048
__global__ void prep_big(const float* __restrict__ B, const float* __restrict__ C,
                         const float* __restrict__ u,
                         const float* __restrict__ Lre, const float* __restrict__ Lim,
                         const float* __restrict__ log_step) {
    int bid = blockIdx.x;
    if (bid < PREPW_BLOCKS) {
        int idx = bid * blockDim.x + threadIdx.x;  // 0 .. P*H-1
        {   // W1 from B: idx = p*H + h
            int p = idx >> 10;
            int h = idx & (H_DIM - 1);
            float lr = Lre[p], li = Lim[p];
            float dt = expf(log_step[p]);
            float ar = lr * dt, ai = li * dt;
            float er = expf(ar);
            float lam_r = er * cosf(ai), lam_i = er * sinf(ai);
            float nr = lam_r - 1.0f, ni = lam_i;
            float den = lr * lr + li * li;
            float gx = (nr * lr + ni * li) / den;
            float gy = (ni * lr - nr * li) / den;
            float2 b = reinterpret_cast<const float2*>(B)[idx];
            float vr = gx * b.x - gy * b.y;
            float vi = gy * b.x + gx * b.y;
            g_W1[p * KDIM + h]           = __float2half_rn(vr);
            g_W1[(P_DIM + p) * KDIM + h] = __float2half_rn(vi);
        }
        {   // W2 from C: idx = h*P + p
            int h = idx >> 9;
            int p = idx & (P_DIM - 1);
            float2 c = reinterpret_cast<const float2*>(C)[idx];
            g_W2[h * N2P + p]         = __float2half_rn(2.0f * c.x);
            g_W2[h * N2P + P_DIM + p] = __float2half_rn(-2.0f * c.y);
        }
    } else {
        int i = (bid - PREPW_BLOCKS) * blockDim.x + threadIdx.x;  // float4 idx
        float4 v = reinterpret_cast<const float4*>(u)[i];
        __half2 a = __floats2half2_rn(v.x, v.y);
        __half2 b = __floats2half2_rn(v.z, v.w);
        uint2 pk = make_uint2(*(uint32_t*)&a, *(uint32_t*)&b);
        reinterpret_cast<uint2*>(g_uh)[i] = pk;
    }
}

// ---------------- mma.sync fp16 GEMM (unchanged control) ----------------
#define BK 64
#define NSTG 3
#define PLANE_B (128 * 128)           // 16384
#define STAGE_B (2 * PLANE_B)         // 32768
#define SMEM_TOT (NSTG * STAGE_B)     // 98304

__device__ __forceinline__ void stage_load(uint32_t sb, int stage,
        const __half* __restrict__ pA, const __half* __restrict__ pB,
        int k0, int tid) {
    uint32_t base = sb + stage * STAGE_B;
#pragma unroll
    for (int i = 0; i < 4; i++) {
        int id = tid + i * 256;               // 0..1023
        int row = id >> 3, ch = id & 7;
        uint32_t dst = base + (uint32_t)(row * 128 + ((ch ^ (row & 7)) << 4));
        size_t gof = (size_t)row * KDIM + k0 + ch * 8;
        cp_async16(dst,           pA + gof);
        cp_async16(dst + PLANE_B, pB + gof);
    }
}

template <bool EPI>
__global__ void __launch_bounds__(256, 2) mma_gemm(
    const __half* __restrict__ A, const __half* __restrict__ Bm,
    void* __restrict__ Co,
    const __half* __restrict__ U, const float* __restrict__ Dv) {
    extern __shared__ __align__(128) char smem[];
    const uint32_t sb = smem_u32(smem);
    const int tid = threadIdx.x;
    const int lane = tid & 31, wid = tid >> 5;
    const int wm = wid & 1, wn = wid >> 1;           // 2x4 warp grid, 64x32 warptile
    const int lq = lane >> 2, lc = lane & 3;
    const int brow = blockIdx.y, bcol = blockIdx.x;

    const __half* pA = A  + (size_t)brow * 128 * KDIM;
    const __half* pB = Bm + (size_t)bcol * 128 * KDIM;

    const int arow = (lane & 7) + ((lane >> 3) & 1) * 8;
    const int akb  = (lane >> 4) & 1;
    const int axor = arow & 7;
    const int brow_l = (lane & 7) + ((lane >> 4) & 1) * 8;
    const int bkb    = (lane >> 3) & 1;
    const int bxor   = brow_l & 7;

    const uint32_t abase = (uint32_t)((wm * 64 + arow) * 128);
    const uint32_t bbase = PLANE_B + (uint32_t)((wn * 32 + brow_l) * 128);

    float acc[4][4][4] = {};
    uint32_t ah[2][4][4], bh[2][2][4];

    stage_load(sb, 0, pA, pB, 0, tid);    CP_COMMIT();
    stage_load(sb, 1, pA, pB, BK, tid);   CP_COMMIT();

    const int NS = KDIM / BK;     // 16
    int sidx = 0;
    for (int s = 0; s < NS; s++) {
        CP_WAIT(1);
        __syncthreads();
        if (s + 2 < NS) {
            int tgt = sidx + 2; if (tgt >= NSTG) tgt -= NSTG;
            stage_load(sb, tgt, pA, pB, (s + 2) * BK, tid);
        }
        CP_COMMIT();

        const uint32_t st = sb + sidx * STAGE_B;

#pragma unroll
        for (int mt = 0; mt < 4; mt++)
            ldsm_x4(ah[0][mt], st + abase + (uint32_t)(mt * 16 * 128)
                               + (uint32_t)((akb ^ axor) << 4));
#pragma unroll
        for (int ntp = 0; ntp < 2; ntp++)
            ldsm_x4(bh[0][ntp], st + bbase + (uint32_t)(ntp * 16 * 128)
                               + (uint32_t)((bkb ^ bxor) << 4));

#pragma unroll
        for (int k16 = 0; k16 < 4; k16++) {
            const int cur = k16 & 1, nxt = cur ^ 1;
            if (k16 < 3) {
                const int kn = k16 + 1;
#pragma unroll
                for (int mt = 0; mt < 4; mt++)
                    ldsm_x4(ah[nxt][mt], st + abase + (uint32_t)(mt * 16 * 128)
                                       + (uint32_t)(((kn * 2 + akb) ^ axor) << 4));
#pragma unroll
                for (int ntp = 0; ntp < 2; ntp++)
                    ldsm_x4(bh[nxt][ntp], st + bbase + (uint32_t)(ntp * 16 * 128)
                                        + (uint32_t)(((kn * 2 + bkb) ^ bxor) << 4));
            }
#pragma unroll
            for (int ntp = 0; ntp < 2; ntp++)
#pragma unroll
                for (int sub = 0; sub < 2; sub++) {
                    const uint32_t* bp = &bh[cur][ntp][sub * 2];
#pragma unroll
                    for (int mt = 0; mt < 4; mt++)
                        mma16816(acc[mt][ntp * 2 + sub], ah[cur][mt], bp);
                }
        }
        sidx++; if (sidx == NSTG) sidx = 0;
    }

    // epilogue
#pragma unroll
    for (int mt = 0; mt < 4; mt++) {
        const int row0 = brow * 128 + wm * 64 + mt * 16 + lq;
#pragma unroll
        for (int nt = 0; nt < 4; nt++) {
            const int col = bcol * 128 + wn * 32 + nt * 8 + lc * 2;
            const float* d = acc[mt][nt];
            if (EPI) {
                float* o = (float*)Co;
                float2 dd = *reinterpret_cast<const float2*>(Dv + col);
                __half2 uh0 = *reinterpret_cast<const __half2*>(U + (size_t)row0 * 1024 + col);
                __half2 uh1 = *reinterpret_cast<const __half2*>(U + (size_t)(row0 + 8) * 1024 + col);
                float2 u0 = __half22float2(uh0);
                float2 u1 = __half22float2(uh1);
                float2 v0 = make_float2(fmaf(dd.x, u0.x, d[0]), fmaf(dd.y, u0.y, d[1]));
                float2 v1 = make_float2(fmaf(dd.x, u1.x, d[2]), fmaf(dd.y, u1.y, d[3]));
                *reinterpret_cast<float2*>(o + (size_t)row0 * 1024 + col) = v0;
                *reinterpret_cast<float2*>(o + (size_t)(row0 + 8) * 1024 + col) = v1;
            } else {
                __half* o = (__half*)Co;
                __half2 h0 = __floats2half2_rn(d[0], d[1]);
                __half2 h1 = __floats2half2_rn(d[2], d[3]);
                *reinterpret_cast<__half2*>(o + (size_t)row0 * 1024 + col) = h0;
                *reinterpret_cast<__half2*>(o + (size_t)(row0 + 8) * 1024 + col) = h1;
            }
        }
    }
}

// ---------------- single-pass scan with parallel lookback ----------------
// Grid = NCHUNK blocks x 512 threads (1 p each). All blocks fit in one wave
// (4 blocks/SM possible by threads) so spin-polling cannot deadlock.
__global__ void __launch_bounds__(512) scan_all() {
    const int c = blockIdx.x;
    const int p = threadIdx.x;
    const float2 lam = g_lam[p];
    const __half* base = g_Bu + (size_t)(c * CHUNK) * N2P;

    // ---- pass 1: local aggregate, batch-8 prefetch (compile-time indexed)
    float br = 0.f, bi = 0.f;
    for (int g = 0; g < CHUNK / 8; g++) {
        float ur[8], ui[8];
#pragma unroll
        for (int j = 0; j < 8; j++) {
            ur[j] = __half2float(base[(g * 8 + j) * N2P + p]);
            ui[j] = __half2float(base[(g * 8 + j) * N2P + P_DIM + p]);
        }
#pragma unroll
        for (int j = 0; j < 8; j++) {
            float nr = fmaf(lam.x, br, fmaf(-lam.y, bi, ur[j]));
            float ni = fmaf(lam.x, bi, fmaf(lam.y, br, ui[j]));
            br = nr; bi = ni;
        }
    }
    g_carry[c * P_DIM + p] = make_float2(br, bi);
    __threadfence();                       // release carries
    __syncthreads();
    if (threadIdx.x == 0) atomicExch(&g_flag[c], 1);

    // ---- lookback: wait for all predecessor flags (parallel poll), then
    //      compute exclusive prefix s = sum_j A^(c-1-j) b_j via s = A*s + b_j.
    float sr = 0.f, si = 0.f;
    if (c > 0) {
        volatile int* vf = g_flag;
        for (int j = p; j < c; j += 512)
            while (vf[j] == 0) {}
        __syncthreads();
        __threadfence();                   // acquire carries

        const float2 Ap = g_lampow[p];
        for (int j0 = 0; j0 < c; j0 += 4) {
            float2 v[4];
#pragma unroll
            for (int k = 0; k < 4; k++)
                v[k] = (j0 + k < c) ? g_carry[(j0 + k) * P_DIM + p]
                                    : make_float2(0.f, 0.f);
#pragma unroll
            for (int k = 0; k < 4; k++) {
                if (j0 + k < c) {
                    float nr = fmaf(Ap.x, sr, fmaf(-Ap.y, si, v[k].x));
                    float ni = fmaf(Ap.x, si, fmaf(Ap.y, sr, v[k].y));
                    sr = nr; si = ni;
                }
            }
        }
    }

    // ---- pass 2: rescan chunk with carry-in (Bu now L2/L1-warm), write xh
    float xr = sr, xi = si;
    __half* oh = g_xh + (size_t)(c * CHUNK) * N2P;
    for (int g = 0; g < CHUNK / 8; g++) {
        float ur[8], ui[8];
#pragma unroll
        for (int j = 0; j < 8; j++) {
            ur[j] = __half2float(base[(g * 8 + j) * N2P + p]);
            ui[j] = __half2float(base[(g * 8 + j) * N2P + P_DIM + p]);
        }
#pragma unroll
        for (int j = 0; j < 8; j++) {
            float nr = fmaf(lam.x, xr, fmaf(-lam.y, xi, ur[j]));
            float ni = fmaf(lam.x, xi, fmaf(lam.y, xr, ui[j]));
            xr = nr; xi = ni;
            oh[(g * 8 + j) * N2P + p]         = __float2half_rn(xr);
            oh[(g * 8 + j) * N2P + P_DIM + p] = __float2half_rn(xi);
        }
    }
}

// ---------------- launcher ----------------
extern "C" void kernel_launch(void* const* d_in, const int* in_sizes, int n_in,
                              void* d_out, int out_size) {
    const float* u        = (const float*)d_in[0];
    const float* Lre      = (const float*)d_in[1];
    const float* Lim      = (const float*)d_in[2];
    const float* B        = (const float*)d_in[3];
    const float* C        = (const float*)d_in[4];
    const float* D        = (const float*)d_in[5];
    const float* log_step = (const float*)d_in[6];
    float* out = (float*)d_out;

    cudaFuncSetAttribute(mma_gemm<false>, cudaFuncAttributeMaxDynamicSharedMemorySize, SMEM_TOT);
    cudaFuncSetAttribute(mma_gemm<true>,  cudaFuncAttributeMaxDynamicSharedMemorySize, SMEM_TOT);

    __half *uh, *w1, *w2, *xh, *bu;
    cudaGetSymbolAddress((void**)&uh, g_uh);
    cudaGetSymbolAddress((void**)&w1, g_W1);
    cudaGetSymbolAddress((void**)&w2, g_W2);
    cudaGetSymbolAddress((void**)&xh, g_xh);
    cudaGetSymbolAddress((void**)&bu, g_Bu);

    prep_lambda<<<1, P_DIM>>>(Lre, Lim, log_step);
    prep_big<<<PREPW_BLOCKS + (L_SEQ * H_DIM / 4) / 256, 256>>>(B, C, u, Lre, Lim, log_step);

    // GEMM1: Bu = u @ W1  (fp16 out)
    mma_gemm<false><<<dim3(N2P / 128, L_SEQ / 128), 256, SMEM_TOT>>>(
        uh, w1, bu, nullptr, nullptr);

    // 4th launch (profiled): fused single-pass scan
    scan_all<<<NCHUNK, P_DIM>>>();

    // GEMM2: out = xs @ W2 + D .* u
    mma_gemm<true><<<dim3(H_DIM / 128, L_SEQ / 128), 256, SMEM_TOT>>>(
        xh, w2, out, uh, D);
}